// round 1
// baseline (speedup 1.0000x reference)
#include <cuda_runtime.h>

#define NN  100000
#define EE  1600000
#define IND 128
#define PED 16
#define FIN 144
#define HID 128
#define LAT 64
#define S1  576   // 4*FIN
#define S2  512   // 4*HID
#define SCAN_BLKS ((NN + 1023) / 1024)

// ---------------- scratch (static device globals; no runtime allocation) ----
__device__ float g_T1[(size_t)NN * S1];   // [T0|T1|T2|T3] at width FIN
__device__ float g_T2[(size_t)NN * S2];   // [T0|T1|T2|T3] at width HID
__device__ float g_deg[NN];
__device__ float g_dinv[NN];
__device__ int   g_cnt[NN];
__device__ int   g_inc[NN];
__device__ int   g_rowptr[NN + 1];
__device__ int   g_cursor[NN];
__device__ int   g_bsum[128];
__device__ int   g_bexc[128];
__device__ int   g_csrc[EE];
__device__ float g_cw[EE];
__device__ float g_gsum[HID];

// ---------------- f32x2 packed helpers (sm_103a) ----------------------------
__device__ __forceinline__ unsigned long long pack2(float lo, float hi) {
    unsigned long long p;
    asm("mov.b64 %0, {%1,%2};" : "=l"(p)
        : "r"(__float_as_uint(lo)), "r"(__float_as_uint(hi)));
    return p;
}
__device__ __forceinline__ void unpack2(unsigned long long p, float& lo, float& hi) {
    unsigned int a, b;
    asm("mov.b64 {%0,%1}, %2;" : "=r"(a), "=r"(b) : "l"(p));
    lo = __uint_as_float(a); hi = __uint_as_float(b);
}
__device__ __forceinline__ unsigned long long fma2(unsigned long long a,
                                                   unsigned long long b,
                                                   unsigned long long c) {
    unsigned long long d;
    asm("fma.rn.f32x2 %0, %1, %2, %3;" : "=l"(d) : "l"(a), "l"(b), "l"(c));
    return d;
}

// ---------------- preprocessing kernels -------------------------------------
__global__ void zero_kernel() {
    int i = blockIdx.x * blockDim.x + threadIdx.x;
    if (i < NN) { g_deg[i] = 0.f; g_cnt[i] = 0; }
    if (i < HID) g_gsum[i] = 0.f;
}

__global__ void deg_cnt_kernel(const int* __restrict__ ei, const float* __restrict__ ew) {
    int e = blockIdx.x * blockDim.x + threadIdx.x;
    if (e >= EE) return;
    int s = ei[e], d = ei[EE + e];
    float w = ew[e];
    if (s == d) w = 0.f;                 // ChebConv removes self loops
    atomicAdd(&g_deg[s], w);
    atomicAdd(&g_cnt[d], 1);
}

__global__ void dinv_kernel() {
    int i = blockIdx.x * blockDim.x + threadIdx.x;
    if (i >= NN) return;
    float dg = g_deg[i];
    g_dinv[i] = (dg > 0.f) ? rsqrtf(dg) : 0.f;
}

__global__ void scan1_kernel(int n) {
    __shared__ int sh[1024];
    int tid = threadIdx.x;
    int i = blockIdx.x * 1024 + tid;
    int v = (i < n) ? g_cnt[i] : 0;
    sh[tid] = v;
    __syncthreads();
    for (int off = 1; off < 1024; off <<= 1) {
        int t = (tid >= off) ? sh[tid - off] : 0;
        __syncthreads();
        sh[tid] += t;
        __syncthreads();
    }
    if (i < n) g_inc[i] = sh[tid];
    if (tid == 1023) g_bsum[blockIdx.x] = sh[1023];
}

__global__ void scan2_kernel(int nb) {
    __shared__ int sh[128];
    int tid = threadIdx.x;
    int v = (tid < nb) ? g_bsum[tid] : 0;
    sh[tid] = v;
    __syncthreads();
    for (int off = 1; off < 128; off <<= 1) {
        int t = (tid >= off) ? sh[tid - off] : 0;
        __syncthreads();
        sh[tid] += t;
        __syncthreads();
    }
    if (tid < nb) g_bexc[tid] = sh[tid] - v;   // exclusive block offsets
}

__global__ void scan3_kernel(int n) {
    int i = blockIdx.x * 1024 + threadIdx.x;
    if (i < n) g_rowptr[i + 1] = g_inc[i] + g_bexc[blockIdx.x];
    if (i == 0) g_rowptr[0] = 0;
}

__global__ void cursor_init_kernel() {
    int i = blockIdx.x * blockDim.x + threadIdx.x;
    if (i < NN) g_cursor[i] = g_rowptr[i];
}

__global__ void scatter_kernel(const int* __restrict__ ei, const float* __restrict__ ew) {
    int e = blockIdx.x * blockDim.x + threadIdx.x;
    if (e >= EE) return;
    int s = ei[e], d = ei[EE + e];
    float w = ew[e];
    if (s == d) w = 0.f;
    float wh = -g_dinv[s] * w * g_dinv[d];   // L_hat = -D^-1/2 A D^-1/2
    int pos = atomicAdd(&g_cursor[d], 1);
    g_csrc[pos] = s;
    g_cw[pos]   = wh;
}

__global__ void build_h0_kernel(const float* __restrict__ x, const float* __restrict__ pe) {
    int idx = blockIdx.x * blockDim.x + threadIdx.x;
    if (idx >= NN * FIN) return;
    int i = idx / FIN, f = idx - i * FIN;
    float v = (f < IND) ? x[i * IND + f] : pe[i * PED + (f - IND)];
    g_T1[(size_t)i * S1 + f] = v;
}

// ---------------- SpMM: out = prop(in) (optionally 2*prop(in)-prev) ---------
__global__ void spmm_kernel(int whichBuf, int S, int F,
                            int inOff, int outOff, int prevOff, int recur) {
    float* T = whichBuf ? g_T2 : g_T1;
    int i = blockIdx.x;
    int f = threadIdx.x;
    if (f >= F) return;
    int beg = g_rowptr[i], end = g_rowptr[i + 1];
    float a0 = 0.f, a1 = 0.f, a2 = 0.f, a3 = 0.f;
    int e = beg;
    for (; e + 4 <= end; e += 4) {
        int s0 = g_csrc[e],     s1 = g_csrc[e + 1];
        int s2 = g_csrc[e + 2], s3 = g_csrc[e + 3];
        float w0 = g_cw[e],     w1 = g_cw[e + 1];
        float w2 = g_cw[e + 2], w3 = g_cw[e + 3];
        a0 += w0 * T[s0 * S + inOff + f];
        a1 += w1 * T[s1 * S + inOff + f];
        a2 += w2 * T[s2 * S + inOff + f];
        a3 += w3 * T[s3 * S + inOff + f];
    }
    for (; e < end; ++e)
        a0 += g_cw[e] * T[g_csrc[e] * S + inOff + f];
    float acc = (a0 + a1) + (a2 + a3);
    float outv = recur ? (2.0f * acc - T[(size_t)i * S + prevOff + f]) : acc;
    T[(size_t)i * S + outOff + f] = outv;
}

// ---------------- fused SGEMM (f32x2): C = relu(A @ B + bias) ---------------
// MODE 0: A = g_T1 [M, K=576], write result into g_T2 slice 0 (stride S2)
// MODE 1: A = g_T2 [M, K=512], column-sum relu output into g_gsum (no store)
template <int MODE>
__global__ void __launch_bounds__(256)
gemm_kernel(const float* __restrict__ B, const float* __restrict__ bias, int K) {
    const int M = NN;
    const float* A = (MODE == 0) ? g_T1 : g_T2;
    __shared__ float As[8][128];
    __shared__ float Bs[8][128];
    int tid = threadIdx.x;
    int blockM = blockIdx.x * 128;
    int ty = tid >> 4, tx = tid & 15;
    int aRow = tid >> 1;
    int aK = (tid & 1) * 4;
    int bRow = tid >> 5;
    int bCol = (tid & 31) * 4;
    unsigned long long acc[8][4];
#pragma unroll
    for (int i = 0; i < 8; i++)
#pragma unroll
        for (int j = 0; j < 4; j++) acc[i][j] = 0ull;

    int gr = blockM + aRow;
    for (int kt = 0; kt < K; kt += 8) {
        float4 av = make_float4(0.f, 0.f, 0.f, 0.f);
        if (gr < M) av = *reinterpret_cast<const float4*>(&A[(size_t)gr * K + kt + aK]);
        float4 bv = *reinterpret_cast<const float4*>(&B[(size_t)(kt + bRow) * HID + bCol]);
        __syncthreads();
        As[aK + 0][aRow] = av.x;
        As[aK + 1][aRow] = av.y;
        As[aK + 2][aRow] = av.z;
        As[aK + 3][aRow] = av.w;
        *reinterpret_cast<float4*>(&Bs[bRow][bCol]) = bv;
        __syncthreads();
#pragma unroll
        for (int kk = 0; kk < 8; kk++) {
            float4 a0 = *reinterpret_cast<const float4*>(&As[kk][ty * 8]);
            float4 a1 = *reinterpret_cast<const float4*>(&As[kk][ty * 8 + 4]);
            float4 b0 = *reinterpret_cast<const float4*>(&Bs[kk][tx * 8]);
            float4 b1 = *reinterpret_cast<const float4*>(&Bs[kk][tx * 8 + 4]);
            unsigned long long bp[4];
            bp[0] = pack2(b0.x, b0.y);
            bp[1] = pack2(b0.z, b0.w);
            bp[2] = pack2(b1.x, b1.y);
            bp[3] = pack2(b1.z, b1.w);
            float aa[8] = {a0.x, a0.y, a0.z, a0.w, a1.x, a1.y, a1.z, a1.w};
#pragma unroll
            for (int i = 0; i < 8; i++) {
                unsigned long long ad = pack2(aa[i], aa[i]);
#pragma unroll
                for (int j = 0; j < 4; j++)
                    acc[i][j] = fma2(ad, bp[j], acc[i][j]);
            }
        }
    }

    if (MODE == 0) {
#pragma unroll
        for (int i = 0; i < 8; i++) {
            int r = blockM + ty * 8 + i;
            if (r < M) {
#pragma unroll
                for (int j = 0; j < 4; j++) {
                    float v0, v1; unpack2(acc[i][j], v0, v1);
                    int c = tx * 8 + j * 2;
                    v0 = fmaxf(v0 + bias[c], 0.f);
                    v1 = fmaxf(v1 + bias[c + 1], 0.f);
                    g_T2[(size_t)r * S2 + c]     = v0;
                    g_T2[(size_t)r * S2 + c + 1] = v1;
                }
            }
        }
    } else {
        __syncthreads();
        float* cs = &As[0][0];
        if (tid < 128) cs[tid] = 0.f;
        __syncthreads();
#pragma unroll
        for (int j = 0; j < 4; j++) {
            int c = tx * 8 + j * 2;
            float bb0 = bias[c], bb1 = bias[c + 1];
            float p0 = 0.f, p1 = 0.f;
#pragma unroll
            for (int i = 0; i < 8; i++) {
                int r = blockM + ty * 8 + i;
                if (r < M) {
                    float v0, v1; unpack2(acc[i][j], v0, v1);
                    p0 += fmaxf(v0 + bb0, 0.f);
                    p1 += fmaxf(v1 + bb1, 0.f);
                }
            }
            atomicAdd(&cs[c], p0);
            atomicAdd(&cs[c + 1], p1);
        }
        __syncthreads();
        if (tid < 128) atomicAdd(&g_gsum[tid], cs[tid]);
    }
}

// ---------------- head: mu = g@W_mu + b_mu, lv = g@W_lv + b_lv --------------
__global__ void head_kernel(const float* __restrict__ Wmu, const float* __restrict__ bmu,
                            const float* __restrict__ Wlv, const float* __restrict__ blv,
                            float* __restrict__ out, int out_size) {
    int j = threadIdx.x;
    if (j >= 128 || j >= out_size) return;
    const float* W  = (j < 64) ? Wmu : Wlv;
    const float* bb = (j < 64) ? bmu : blv;
    int c = j & 63;
    const float invN = 1.0f / (float)NN;
    float s = 0.f;
#pragma unroll
    for (int f = 0; f < HID; f++)
        s += (g_gsum[f] * invN) * W[f * LAT + c];
    out[j] = s + bb[c];
}

// ---------------- launch -----------------------------------------------------
extern "C" void kernel_launch(void* const* d_in, const int* in_sizes, int n_in,
                              void* d_out, int out_size) {
    const float* x   = (const float*)d_in[0];
    const int*   ei  = (const int*)  d_in[1];
    const float* pe  = (const float*)d_in[2];
    const float* ew  = (const float*)d_in[3];
    const float* W1  = (const float*)d_in[4];
    const float* b1  = (const float*)d_in[5];
    const float* W2  = (const float*)d_in[6];
    const float* b2  = (const float*)d_in[7];
    const float* Wmu = (const float*)d_in[8];
    const float* bmu = (const float*)d_in[9];
    const float* Wlv = (const float*)d_in[10];
    const float* blv = (const float*)d_in[11];
    float* out = (float*)d_out;

    zero_kernel<<<(NN + 255) / 256, 256>>>();
    deg_cnt_kernel<<<(EE + 255) / 256, 256>>>(ei, ew);
    dinv_kernel<<<(NN + 255) / 256, 256>>>();
    scan1_kernel<<<SCAN_BLKS, 1024>>>(NN);
    scan2_kernel<<<1, 128>>>(SCAN_BLKS);
    scan3_kernel<<<SCAN_BLKS, 1024>>>(NN);
    cursor_init_kernel<<<(NN + 255) / 256, 256>>>();
    scatter_kernel<<<(EE + 255) / 256, 256>>>(ei, ew);
    build_h0_kernel<<<(NN * FIN + 255) / 256, 256>>>(x, pe);

    // ---- ChebConv 1 (F=144, stride 576) ----
    spmm_kernel<<<NN, 160>>>(0, S1, FIN, 0,       FIN,     0,   0);  // T1 = L h
    spmm_kernel<<<NN, 160>>>(0, S1, FIN, FIN,     2 * FIN, 0,   1);  // T2 = 2 L T1 - T0
    spmm_kernel<<<NN, 160>>>(0, S1, FIN, 2 * FIN, 3 * FIN, FIN, 1);  // T3 = 2 L T2 - T1
    gemm_kernel<0><<<(NN + 127) / 128, 256>>>(W1, b1, S1);           // relu -> g_T2 slice0

    // ---- ChebConv 2 (F=128, stride 512) ----
    spmm_kernel<<<NN, 128>>>(1, S2, HID, 0,       HID,     0,   0);
    spmm_kernel<<<NN, 128>>>(1, S2, HID, HID,     2 * HID, 0,   1);
    spmm_kernel<<<NN, 128>>>(1, S2, HID, 2 * HID, 3 * HID, HID, 1);
    gemm_kernel<1><<<(NN + 127) / 128, 256>>>(W2, b2, S2);           // relu + column-sum

    head_kernel<<<1, 128>>>(Wmu, bmu, Wlv, blv, out, out_size);
}

// round 3
// speedup vs baseline: 2.8226x; 2.8226x over previous
#include <cuda_runtime.h>
#include <cstdint>

#define NN  100000
#define EE  1600000
#define IND 128
#define PED 16
#define FIN 144
#define HID 128
#define LAT 64
#define S1  576   // 4*FIN
#define S2  512   // 4*HID
#define SCAN_BLKS ((NN + 1023) / 1024)

// ---------------- scratch (static device globals; no runtime allocation) ----
__device__ float g_T1[(size_t)NN * S1];   // [T0|T1|T2|T3] at width FIN
__device__ float g_T2[(size_t)NN * S2];   // [T0|T1|T2|T3] at width HID
__device__ float g_deg[NN];
__device__ float g_dinv[NN];
__device__ int   g_cnt[NN];
__device__ int   g_inc[NN];
__device__ int   g_rowptr[NN + 1];
__device__ int   g_cursor[NN];
__device__ int   g_bsum[128];
__device__ int   g_bexc[128];
__device__ int   g_csrc[EE];
__device__ float g_cw[EE];
__device__ float g_gsum[HID];

// ---------------- helpers ----------------------------------------------------
__device__ __forceinline__ uint32_t f2tf32(float v) {
    uint32_t u;
    asm("cvt.rna.tf32.f32 %0, %1;" : "=r"(u) : "f"(v));
    return u;
}
__device__ __forceinline__ void mma_tf32(float* d, const uint32_t* a, const uint32_t* b) {
    asm volatile(
        "mma.sync.aligned.m16n8k8.row.col.f32.tf32.tf32.f32 "
        "{%0,%1,%2,%3}, {%4,%5,%6,%7}, {%8,%9}, {%0,%1,%2,%3};"
        : "+f"(d[0]), "+f"(d[1]), "+f"(d[2]), "+f"(d[3])
        : "r"(a[0]), "r"(a[1]), "r"(a[2]), "r"(a[3]), "r"(b[0]), "r"(b[1]));
}

// ---------------- preprocessing kernels -------------------------------------
__global__ void zero_kernel() {
    int i = blockIdx.x * blockDim.x + threadIdx.x;
    if (i < NN) { g_deg[i] = 0.f; g_cnt[i] = 0; }
    if (i < HID) g_gsum[i] = 0.f;
}

__global__ void deg_cnt_kernel(const int* __restrict__ ei, const float* __restrict__ ew) {
    int e = blockIdx.x * blockDim.x + threadIdx.x;
    if (e >= EE) return;
    int s = ei[e], d = ei[EE + e];
    float w = ew[e];
    if (s == d) w = 0.f;                 // ChebConv removes self loops
    atomicAdd(&g_deg[s], w);
    atomicAdd(&g_cnt[d], 1);
}

__global__ void dinv_kernel() {
    int i = blockIdx.x * blockDim.x + threadIdx.x;
    if (i >= NN) return;
    float dg = g_deg[i];
    g_dinv[i] = (dg > 0.f) ? rsqrtf(dg) : 0.f;
}

__global__ void scan1_kernel(int n) {
    __shared__ int sh[1024];
    int tid = threadIdx.x;
    int i = blockIdx.x * 1024 + tid;
    int v = (i < n) ? g_cnt[i] : 0;
    sh[tid] = v;
    __syncthreads();
    for (int off = 1; off < 1024; off <<= 1) {
        int t = (tid >= off) ? sh[tid - off] : 0;
        __syncthreads();
        sh[tid] += t;
        __syncthreads();
    }
    if (i < n) g_inc[i] = sh[tid];
    if (tid == 1023) g_bsum[blockIdx.x] = sh[1023];
}

__global__ void scan2_kernel(int nb) {
    __shared__ int sh[128];
    int tid = threadIdx.x;
    int v = (tid < nb) ? g_bsum[tid] : 0;
    sh[tid] = v;
    __syncthreads();
    for (int off = 1; off < 128; off <<= 1) {
        int t = (tid >= off) ? sh[tid - off] : 0;
        __syncthreads();
        sh[tid] += t;
        __syncthreads();
    }
    if (tid < nb) g_bexc[tid] = sh[tid] - v;   // exclusive block offsets
}

__global__ void scan3_kernel(int n) {
    int i = blockIdx.x * 1024 + threadIdx.x;
    if (i < n) g_rowptr[i + 1] = g_inc[i] + g_bexc[blockIdx.x];
    if (i == 0) g_rowptr[0] = 0;
}

__global__ void cursor_init_kernel() {
    int i = blockIdx.x * blockDim.x + threadIdx.x;
    if (i < NN) g_cursor[i] = g_rowptr[i];
}

__global__ void scatter_kernel(const int* __restrict__ ei, const float* __restrict__ ew) {
    int e = blockIdx.x * blockDim.x + threadIdx.x;
    if (e >= EE) return;
    int s = ei[e], d = ei[EE + e];
    float w = ew[e];
    if (s == d) w = 0.f;
    float wh = -g_dinv[s] * w * g_dinv[d];   // L_hat = -D^-1/2 A D^-1/2
    int pos = atomicAdd(&g_cursor[d], 1);
    g_csrc[pos] = s;
    g_cw[pos]   = wh;
}

__global__ void build_h0_kernel(const float* __restrict__ x, const float* __restrict__ pe) {
    int idx = blockIdx.x * blockDim.x + threadIdx.x;
    if (idx >= NN * FIN) return;
    int i = idx / FIN, f = idx - i * FIN;
    float v = (f < IND) ? x[i * IND + f] : pe[i * PED + (f - IND)];
    g_T1[(size_t)i * S1 + f] = v;
}

// ---------------- SpMM (float4): out = prop(in) or 2*prop(in)-prev ----------
// LANES float4-lanes per row, 4 rows per block. blockDim = 4*LANES.
__global__ void spmm4_kernel(int whichBuf, int S, int LANES,
                             int inOff, int outOff, int prevOff, int recur) {
    float* T = whichBuf ? g_T2 : g_T1;
    int tid = threadIdx.x;
    int r  = tid / LANES;
    int f4 = tid - r * LANES;
    int i = blockIdx.x * 4 + r;
    if (i >= NN) return;
    int beg = g_rowptr[i], end = g_rowptr[i + 1];
    float ax = 0.f, ay = 0.f, az = 0.f, aw = 0.f;
    float bx = 0.f, by = 0.f, bz = 0.f, bw = 0.f;
    int e = beg;
    for (; e + 2 <= end; e += 2) {
        int s0 = g_csrc[e], s1 = g_csrc[e + 1];
        float w0 = g_cw[e], w1 = g_cw[e + 1];
        const float4 v0 = *reinterpret_cast<const float4*>(&T[(size_t)s0 * S + inOff + f4 * 4]);
        const float4 v1 = *reinterpret_cast<const float4*>(&T[(size_t)s1 * S + inOff + f4 * 4]);
        ax += w0 * v0.x; ay += w0 * v0.y; az += w0 * v0.z; aw += w0 * v0.w;
        bx += w1 * v1.x; by += w1 * v1.y; bz += w1 * v1.z; bw += w1 * v1.w;
    }
    if (e < end) {
        int s0 = g_csrc[e];
        float w0 = g_cw[e];
        const float4 v0 = *reinterpret_cast<const float4*>(&T[(size_t)s0 * S + inOff + f4 * 4]);
        ax += w0 * v0.x; ay += w0 * v0.y; az += w0 * v0.z; aw += w0 * v0.w;
    }
    float4 o;
    o.x = ax + bx; o.y = ay + by; o.z = az + bz; o.w = aw + bw;
    if (recur) {
        const float4 p = *reinterpret_cast<const float4*>(&T[(size_t)i * S + prevOff + f4 * 4]);
        o.x = 2.f * o.x - p.x; o.y = 2.f * o.y - p.y;
        o.z = 2.f * o.z - p.z; o.w = 2.f * o.w - p.w;
    }
    *reinterpret_cast<float4*>(&T[(size_t)i * S + outOff + f4 * 4]) = o;
}

// ---------------- tf32 mma.sync GEMM -----------------------------------------
// C[128x128 tile] = relu(A @ W + bias)
// MODE 0: A = g_T1 [NN, K=576]; write to g_T2 slice0 (stride S2)
// MODE 1: A = g_T2 [NN, K=512]; column-sum into g_gsum (no store of C)
// W is [K][128] row-major (native layout) == B in [k][n] form.
template <int MODE, int K, int NKT>
__global__ void __launch_bounds__(256)
mma_gemm_kernel(const float* __restrict__ W, const float* __restrict__ bias) {
    const float* A = (MODE == 0) ? g_T1 : g_T2;
    __shared__ uint32_t As[128 * 36];   // [row][k] pad 36
    __shared__ uint32_t Bs[32 * 132];   // [k][n]  pad 132
    __shared__ float cs[128];

    int tid = threadIdx.x;
    int lane = tid & 31, wid = tid >> 5;
    int wm = (wid & 1) * 64;        // warp M offset
    int wn = (wid >> 1) * 32;       // warp N offset
    int blockM = blockIdx.x * 128;
    int g = lane >> 2, c = lane & 3;

    float acc[4][4][4];
#pragma unroll
    for (int mt = 0; mt < 4; mt++)
#pragma unroll
        for (int nt = 0; nt < 4; nt++)
#pragma unroll
            for (int q = 0; q < 4; q++) acc[mt][nt][q] = 0.f;

    if (MODE == 1 && tid < 128) cs[tid] = 0.f;

    for (int kt = 0; kt < NKT; kt++) {
        int kc = kt * 32;
        __syncthreads();
        // load A tile: 128 rows x 32 k
#pragma unroll
        for (int it = 0; it < 4; it++) {
            int idx = tid + it * 256;
            int row = idx >> 3, q = idx & 7;
            int gr = blockM + row;
            float4 v = make_float4(0.f, 0.f, 0.f, 0.f);
            if (gr < NN)
                v = *reinterpret_cast<const float4*>(&A[(size_t)gr * K + kc + q * 4]);
            uint32_t* d = &As[row * 36 + q * 4];
            d[0] = f2tf32(v.x); d[1] = f2tf32(v.y);
            d[2] = f2tf32(v.z); d[3] = f2tf32(v.w);
        }
        // load B tile: 32 k x 128 n
#pragma unroll
        for (int it = 0; it < 4; it++) {
            int idx = tid + it * 256;
            int kr = idx >> 5, q = idx & 31;
            float4 v = *reinterpret_cast<const float4*>(&W[(size_t)(kc + kr) * 128 + q * 4]);
            uint32_t* d = &Bs[kr * 132 + q * 4];
            d[0] = f2tf32(v.x); d[1] = f2tf32(v.y);
            d[2] = f2tf32(v.z); d[3] = f2tf32(v.w);
        }
        __syncthreads();
#pragma unroll
        for (int kk = 0; kk < 4; kk++) {
            int k0 = kk * 8;
            uint32_t a[4][4];
#pragma unroll
            for (int mt = 0; mt < 4; mt++) {
                int row = wm + mt * 16 + g;
                a[mt][0] = As[row * 36 + k0 + c];
                a[mt][1] = As[(row + 8) * 36 + k0 + c];
                a[mt][2] = As[row * 36 + k0 + c + 4];
                a[mt][3] = As[(row + 8) * 36 + k0 + c + 4];
            }
            uint32_t b[4][2];
#pragma unroll
            for (int nt = 0; nt < 4; nt++) {
                int col = wn + nt * 8 + g;
                b[nt][0] = Bs[(k0 + c) * 132 + col];
                b[nt][1] = Bs[(k0 + c + 4) * 132 + col];
            }
#pragma unroll
            for (int mt = 0; mt < 4; mt++)
#pragma unroll
                for (int nt = 0; nt < 4; nt++)
                    mma_tf32(acc[mt][nt], a[mt], b[nt]);
        }
    }

    // ---- epilogue ----
    if (MODE == 0) {
#pragma unroll
        for (int mt = 0; mt < 4; mt++) {
#pragma unroll
            for (int nt = 0; nt < 4; nt++) {
                int col = wn + nt * 8 + 2 * c;
                float b0 = bias[col], b1 = bias[col + 1];
                int row0 = blockM + wm + mt * 16 + g;
                int row1 = row0 + 8;
                if (row0 < NN) {
                    float2 o;
                    o.x = fmaxf(acc[mt][nt][0] + b0, 0.f);
                    o.y = fmaxf(acc[mt][nt][1] + b1, 0.f);
                    *reinterpret_cast<float2*>(&g_T2[(size_t)row0 * S2 + col]) = o;
                }
                if (row1 < NN) {
                    float2 o;
                    o.x = fmaxf(acc[mt][nt][2] + b0, 0.f);
                    o.y = fmaxf(acc[mt][nt][3] + b1, 0.f);
                    *reinterpret_cast<float2*>(&g_T2[(size_t)row1 * S2 + col]) = o;
                }
            }
        }
    } else {
#pragma unroll
        for (int nt = 0; nt < 4; nt++) {
            int col = wn + nt * 8 + 2 * c;
            float b0 = bias[col], b1 = bias[col + 1];
            float s0 = 0.f, s1 = 0.f;
#pragma unroll
            for (int mt = 0; mt < 4; mt++) {
                int row0 = blockM + wm + mt * 16 + g;
                int row1 = row0 + 8;
                if (row0 < NN) {
                    s0 += fmaxf(acc[mt][nt][0] + b0, 0.f);
                    s1 += fmaxf(acc[mt][nt][1] + b1, 0.f);
                }
                if (row1 < NN) {
                    s0 += fmaxf(acc[mt][nt][2] + b0, 0.f);
                    s1 += fmaxf(acc[mt][nt][3] + b1, 0.f);
                }
            }
            // reduce across g (lanes differing in bits 2..4)
#pragma unroll
            for (int o = 4; o < 32; o <<= 1) {
                s0 += __shfl_xor_sync(0xffffffffu, s0, o);
                s1 += __shfl_xor_sync(0xffffffffu, s1, o);
            }
            if (g == 0) {
                atomicAdd(&cs[col], s0);
                atomicAdd(&cs[col + 1], s1);
            }
        }
        __syncthreads();
        if (tid < 128) atomicAdd(&g_gsum[tid], cs[tid]);
    }
}

// ---------------- head: mu = g@W_mu + b_mu, lv = g@W_lv + b_lv --------------
__global__ void head_kernel(const float* __restrict__ Wmu, const float* __restrict__ bmu,
                            const float* __restrict__ Wlv, const float* __restrict__ blv,
                            float* __restrict__ out, int out_size) {
    int j = threadIdx.x;
    if (j >= 128 || j >= out_size) return;
    const float* W  = (j < 64) ? Wmu : Wlv;
    const float* bb = (j < 64) ? bmu : blv;
    int col = j & 63;
    const float invN = 1.0f / (float)NN;
    float s = 0.f;
#pragma unroll
    for (int f = 0; f < HID; f++)
        s += (g_gsum[f] * invN) * W[f * LAT + col];
    out[j] = s + bb[col];
}

// ---------------- launch -----------------------------------------------------
extern "C" void kernel_launch(void* const* d_in, const int* in_sizes, int n_in,
                              void* d_out, int out_size) {
    const float* x   = (const float*)d_in[0];
    const int*   ei  = (const int*)  d_in[1];
    const float* pe  = (const float*)d_in[2];
    const float* ew  = (const float*)d_in[3];
    const float* W1  = (const float*)d_in[4];
    const float* b1  = (const float*)d_in[5];
    const float* W2  = (const float*)d_in[6];
    const float* b2  = (const float*)d_in[7];
    const float* Wmu = (const float*)d_in[8];
    const float* bmu = (const float*)d_in[9];
    const float* Wlv = (const float*)d_in[10];
    const float* blv = (const float*)d_in[11];
    float* out = (float*)d_out;

    zero_kernel<<<(NN + 255) / 256, 256>>>();
    deg_cnt_kernel<<<(EE + 255) / 256, 256>>>(ei, ew);
    dinv_kernel<<<(NN + 255) / 256, 256>>>();
    scan1_kernel<<<SCAN_BLKS, 1024>>>(NN);
    scan2_kernel<<<1, 128>>>(SCAN_BLKS);
    scan3_kernel<<<SCAN_BLKS, 1024>>>(NN);
    cursor_init_kernel<<<(NN + 255) / 256, 256>>>();
    scatter_kernel<<<(EE + 255) / 256, 256>>>(ei, ew);
    build_h0_kernel<<<(NN * FIN + 255) / 256, 256>>>(x, pe);

    const int GEMM_BLOCKS = (NN + 127) / 128;
    const int SPMM_BLOCKS = (NN + 3) / 4;

    // ---- ChebConv 1 (F=144 -> 36 float4 lanes, stride 576) ----
    spmm4_kernel<<<SPMM_BLOCKS, 144>>>(0, S1, 36, 0,       FIN,     0,   0);
    spmm4_kernel<<<SPMM_BLOCKS, 144>>>(0, S1, 36, FIN,     2 * FIN, 0,   1);
    spmm4_kernel<<<SPMM_BLOCKS, 144>>>(0, S1, 36, 2 * FIN, 3 * FIN, FIN, 1);
    mma_gemm_kernel<0, S1, 18><<<GEMM_BLOCKS, 256>>>(W1, b1);

    // ---- ChebConv 2 (F=128 -> 32 float4 lanes, stride 512) ----
    spmm4_kernel<<<SPMM_BLOCKS, 128>>>(1, S2, 32, 0,       HID,     0,   0);
    spmm4_kernel<<<SPMM_BLOCKS, 128>>>(1, S2, 32, HID,     2 * HID, 0,   1);
    spmm4_kernel<<<SPMM_BLOCKS, 128>>>(1, S2, 32, 2 * HID, 3 * HID, HID, 1);
    mma_gemm_kernel<1, S2, 16><<<GEMM_BLOCKS, 256>>>(W2, b2);

    head_kernel<<<1, 128>>>(Wmu, bmu, Wlv, blv, out, out_size);
}

// round 4
// speedup vs baseline: 4.4738x; 1.5850x over previous
#include <cuda_runtime.h>
#include <cuda_fp16.h>
#include <cstdint>

#define NN  100000
#define EE  1600000
#define IND 128
#define PED 16
#define FIN 144
#define HID 128
#define LAT 64
#define S1  576   // 4*FIN
#define S2  512   // 4*HID
#define SCAN_BLKS ((NN + 1023) / 1024)

// ---------------- scratch (static device globals; no runtime allocation) ----
__device__ __half  g_T1[(size_t)NN * S1];   // [T0|T1|T2|T3] width FIN, fp16
__device__ __half  g_T2[(size_t)NN * S2];   // [T0|T1|T2|T3] width HID, fp16
__device__ __half2 g_W1p[(S1 / 2) * 128];   // W1 packed: [k2][n] = (W[2k2][n], W[2k2+1][n])
__device__ __half2 g_W2p[(S2 / 2) * 128];
__device__ float g_deg[NN];
__device__ float g_dinv[NN];
__device__ int   g_cnt[NN];
__device__ int   g_inc[NN];
__device__ int   g_rowptr[NN + 1];
__device__ int   g_cursor[NN];
__device__ int   g_bsum[128];
__device__ int   g_bexc[128];
__device__ int   g_csrc[EE];
__device__ float g_cw[EE];
__device__ float g_gsum[HID];

// ---------------- helpers ----------------------------------------------------
__device__ __forceinline__ void mma_f16(float* d, const uint32_t* a, const uint32_t* b) {
    asm volatile(
        "mma.sync.aligned.m16n8k16.row.col.f32.f16.f16.f32 "
        "{%0,%1,%2,%3}, {%4,%5,%6,%7}, {%8,%9}, {%0,%1,%2,%3};"
        : "+f"(d[0]), "+f"(d[1]), "+f"(d[2]), "+f"(d[3])
        : "r"(a[0]), "r"(a[1]), "r"(a[2]), "r"(a[3]), "r"(b[0]), "r"(b[1]));
}

// ---------------- preprocessing kernels -------------------------------------
__global__ void zero_kernel() {
    int i = blockIdx.x * blockDim.x + threadIdx.x;
    if (i < NN) { g_deg[i] = 0.f; g_cnt[i] = 0; }
    if (i < HID) g_gsum[i] = 0.f;
}

__global__ void deg_cnt_kernel(const int* __restrict__ ei, const float* __restrict__ ew) {
    int e = blockIdx.x * blockDim.x + threadIdx.x;
    if (e >= EE) return;
    int s = ei[e], d = ei[EE + e];
    float w = ew[e];
    if (s == d) w = 0.f;                 // ChebConv removes self loops
    atomicAdd(&g_deg[s], w);
    atomicAdd(&g_cnt[d], 1);
}

__global__ void dinv_kernel() {
    int i = blockIdx.x * blockDim.x + threadIdx.x;
    if (i >= NN) return;
    float dg = g_deg[i];
    g_dinv[i] = (dg > 0.f) ? rsqrtf(dg) : 0.f;
}

__global__ void scan1_kernel(int n) {
    __shared__ int sh[1024];
    int tid = threadIdx.x;
    int i = blockIdx.x * 1024 + tid;
    int v = (i < n) ? g_cnt[i] : 0;
    sh[tid] = v;
    __syncthreads();
    for (int off = 1; off < 1024; off <<= 1) {
        int t = (tid >= off) ? sh[tid - off] : 0;
        __syncthreads();
        sh[tid] += t;
        __syncthreads();
    }
    if (i < n) g_inc[i] = sh[tid];
    if (tid == 1023) g_bsum[blockIdx.x] = sh[1023];
}

__global__ void scan2_kernel(int nb) {
    __shared__ int sh[128];
    int tid = threadIdx.x;
    int v = (tid < nb) ? g_bsum[tid] : 0;
    sh[tid] = v;
    __syncthreads();
    for (int off = 1; off < 128; off <<= 1) {
        int t = (tid >= off) ? sh[tid - off] : 0;
        __syncthreads();
        sh[tid] += t;
        __syncthreads();
    }
    if (tid < nb) g_bexc[tid] = sh[tid] - v;   // exclusive block offsets
}

__global__ void scan3_kernel(int n) {
    int i = blockIdx.x * 1024 + threadIdx.x;
    if (i < n) {
        int rp = g_inc[i] + g_bexc[blockIdx.x];
        g_rowptr[i + 1] = rp;
    }
    if (i == 0) g_rowptr[0] = 0;
}

__global__ void cursor_init_kernel() {
    int i = blockIdx.x * blockDim.x + threadIdx.x;
    if (i < NN) g_cursor[i] = g_rowptr[i];
}

__global__ void scatter_kernel(const int* __restrict__ ei, const float* __restrict__ ew) {
    int e = blockIdx.x * blockDim.x + threadIdx.x;
    if (e >= EE) return;
    int s = ei[e], d = ei[EE + e];
    float w = ew[e];
    if (s == d) w = 0.f;
    float wh = -g_dinv[s] * w * g_dinv[d];   // L_hat = -D^-1/2 A D^-1/2
    int pos = atomicAdd(&g_cursor[d], 1);
    g_csrc[pos] = s;
    g_cw[pos]   = wh;
}

__global__ void build_h0_kernel(const float* __restrict__ x, const float* __restrict__ pe) {
    int idx = blockIdx.x * blockDim.x + threadIdx.x;
    if (idx >= NN * FIN) return;
    int i = idx / FIN, f = idx - i * FIN;
    float v = (f < IND) ? x[i * IND + f] : pe[i * PED + (f - IND)];
    g_T1[(size_t)i * S1 + f] = __float2half(v);
}

__global__ void packW_kernel(const float* __restrict__ W, int K2, int which) {
    int idx = blockIdx.x * blockDim.x + threadIdx.x;
    if (idx >= K2 * 128) return;
    int k2 = idx >> 7, n = idx & 127;
    __half2 h = __floats2half2_rn(W[(size_t)(2 * k2) * 128 + n],
                                  W[(size_t)(2 * k2 + 1) * 128 + n]);
    (which ? g_W2p : g_W1p)[idx] = h;
}

// ---------------- SpMM (half, uint4 = 8 feats/lane) -------------------------
// LANES uint4-lanes per row, 8 rows per block. blockDim = 8*LANES.
__global__ void spmm8h_kernel(int whichBuf, int S, int LANES,
                              int inOff, int outOff, int prevOff, int recur) {
    __half* T = whichBuf ? g_T2 : g_T1;
    int tid = threadIdx.x;
    int r  = tid / LANES;
    int f8 = tid - r * LANES;
    int i = blockIdx.x * 8 + r;
    if (i >= NN) return;
    int beg = g_rowptr[i], end = g_rowptr[i + 1];
    int fo = inOff + f8 * 8;
    float acc[8];
#pragma unroll
    for (int q = 0; q < 8; q++) acc[q] = 0.f;
    int e = beg;
    for (; e + 2 <= end; e += 2) {
        int s0 = g_csrc[e], s1 = g_csrc[e + 1];
        float w0 = g_cw[e], w1 = g_cw[e + 1];
        uint4 v0 = *reinterpret_cast<const uint4*>(T + (size_t)s0 * S + fo);
        uint4 v1 = *reinterpret_cast<const uint4*>(T + (size_t)s1 * S + fo);
        const __half2* h0 = reinterpret_cast<const __half2*>(&v0);
        const __half2* h1 = reinterpret_cast<const __half2*>(&v1);
#pragma unroll
        for (int q = 0; q < 4; q++) {
            float2 a = __half22float2(h0[q]);
            float2 b = __half22float2(h1[q]);
            acc[2 * q]     += w0 * a.x + w1 * b.x;
            acc[2 * q + 1] += w0 * a.y + w1 * b.y;
        }
    }
    if (e < end) {
        int s0 = g_csrc[e];
        float w0 = g_cw[e];
        uint4 v0 = *reinterpret_cast<const uint4*>(T + (size_t)s0 * S + fo);
        const __half2* h0 = reinterpret_cast<const __half2*>(&v0);
#pragma unroll
        for (int q = 0; q < 4; q++) {
            float2 a = __half22float2(h0[q]);
            acc[2 * q]     += w0 * a.x;
            acc[2 * q + 1] += w0 * a.y;
        }
    }
    if (recur) {
        uint4 pv = *reinterpret_cast<const uint4*>(T + (size_t)i * S + prevOff + f8 * 8);
        const __half2* hp = reinterpret_cast<const __half2*>(&pv);
#pragma unroll
        for (int q = 0; q < 4; q++) {
            float2 p = __half22float2(hp[q]);
            acc[2 * q]     = 2.f * acc[2 * q]     - p.x;
            acc[2 * q + 1] = 2.f * acc[2 * q + 1] - p.y;
        }
    }
    uint4 o;
    __half2* ho = reinterpret_cast<__half2*>(&o);
#pragma unroll
    for (int q = 0; q < 4; q++)
        ho[q] = __floats2half2_rn(acc[2 * q], acc[2 * q + 1]);
    *reinterpret_cast<uint4*>(T + (size_t)i * S + outOff + f8 * 8) = o;
}

// ---------------- fp16 mma.sync GEMM -----------------------------------------
// C[128x128 tile] = relu(A @ W + bias), fp32 accumulate
// MODE 0: A = g_T1 [NN, K=576] half; write half to g_T2 slice0 (stride S2)
// MODE 1: A = g_T2 [NN, K=512] half; column-sum into g_gsum (no store of C)
// Wp is [K/2][128] half2 (k-pairs packed) == B-fragment-native layout.
template <int MODE, int K, int NKT>
__global__ void __launch_bounds__(256)
mma_gemm_kernel(const float* __restrict__ bias) {
    const __half*  A  = (MODE == 0) ? g_T1 : g_T2;
    const __half2* Wp = (MODE == 0) ? g_W1p : g_W2p;
    __shared__ alignas(16) __half  As[128 * 40];   // [row][k], stride 40 halves
    __shared__ alignas(16) __half2 Bs[16 * 136];   // [k2][n],  stride 136 half2
    __shared__ float cs[128];

    int tid = threadIdx.x;
    int lane = tid & 31, wid = tid >> 5;
    int wm = (wid & 1) * 64;        // warp M offset
    int wn = (wid >> 1) * 32;       // warp N offset
    int blockM = blockIdx.x * 128;
    int g = lane >> 2, c = lane & 3;

    const uint32_t* As32 = reinterpret_cast<const uint32_t*>(As);
    const uint32_t* Bs32 = reinterpret_cast<const uint32_t*>(Bs);

    float acc[4][4][4];
#pragma unroll
    for (int mt = 0; mt < 4; mt++)
#pragma unroll
        for (int nt = 0; nt < 4; nt++)
#pragma unroll
            for (int q = 0; q < 4; q++) acc[mt][nt][q] = 0.f;

    if (MODE == 1 && tid < 128) cs[tid] = 0.f;

    for (int kt = 0; kt < NKT; kt++) {
        int kc = kt * 32;       // k offset (halves)
        int kc2 = kt * 16;      // k2 offset (half2 pairs)
        __syncthreads();
        // A tile: 128 rows x 32 k halves = 512 uint4
#pragma unroll
        for (int it = 0; it < 2; it++) {
            int idx = tid + it * 256;
            int row = idx >> 2, q = idx & 3;
            int gr = blockM + row;
            uint4 v = make_uint4(0u, 0u, 0u, 0u);
            if (gr < NN)
                v = *reinterpret_cast<const uint4*>(&A[(size_t)gr * K + kc + q * 8]);
            *reinterpret_cast<uint4*>(&As[row * 40 + q * 8]) = v;
        }
        // B tile: 16 k2 x 128 n half2 = 512 uint4
#pragma unroll
        for (int it = 0; it < 2; it++) {
            int idx = tid + it * 256;
            int kr2 = idx >> 5, n4 = idx & 31;
            uint4 v = *reinterpret_cast<const uint4*>(&Wp[(size_t)(kc2 + kr2) * 128 + n4 * 4]);
            *reinterpret_cast<uint4*>(&Bs[kr2 * 136 + n4 * 4]) = v;
        }
        __syncthreads();
#pragma unroll
        for (int ks = 0; ks < 2; ks++) {    // two k16 steps per 32-chunk
            int k2b = ks * 8;
            uint32_t a[4][4];
#pragma unroll
            for (int mt = 0; mt < 4; mt++) {
                int row = wm + mt * 16 + g;
                a[mt][0] = As32[row * 20 + k2b + c];
                a[mt][1] = As32[(row + 8) * 20 + k2b + c];
                a[mt][2] = As32[row * 20 + k2b + c + 4];
                a[mt][3] = As32[(row + 8) * 20 + k2b + c + 4];
            }
            uint32_t b[4][2];
#pragma unroll
            for (int nt = 0; nt < 4; nt++) {
                int col = wn + nt * 8 + g;
                b[nt][0] = Bs32[(k2b + c) * 136 + col];
                b[nt][1] = Bs32[(k2b + c + 4) * 136 + col];
            }
#pragma unroll
            for (int mt = 0; mt < 4; mt++)
#pragma unroll
                for (int nt = 0; nt < 4; nt++)
                    mma_f16(acc[mt][nt], a[mt], b[nt]);
        }
    }

    // ---- epilogue ----
    if (MODE == 0) {
#pragma unroll
        for (int mt = 0; mt < 4; mt++) {
#pragma unroll
            for (int nt = 0; nt < 4; nt++) {
                int col = wn + nt * 8 + 2 * c;
                float b0 = bias[col], b1 = bias[col + 1];
                int row0 = blockM + wm + mt * 16 + g;
                int row1 = row0 + 8;
                if (row0 < NN) {
                    __half2 o = __floats2half2_rn(fmaxf(acc[mt][nt][0] + b0, 0.f),
                                                  fmaxf(acc[mt][nt][1] + b1, 0.f));
                    *reinterpret_cast<__half2*>(&g_T2[(size_t)row0 * S2 + col]) = o;
                }
                if (row1 < NN) {
                    __half2 o = __floats2half2_rn(fmaxf(acc[mt][nt][2] + b0, 0.f),
                                                  fmaxf(acc[mt][nt][3] + b1, 0.f));
                    *reinterpret_cast<__half2*>(&g_T2[(size_t)row1 * S2 + col]) = o;
                }
            }
        }
    } else {
#pragma unroll
        for (int nt = 0; nt < 4; nt++) {
            int col = wn + nt * 8 + 2 * c;
            float b0 = bias[col], b1 = bias[col + 1];
            float s0 = 0.f, s1 = 0.f;
#pragma unroll
            for (int mt = 0; mt < 4; mt++) {
                int row0 = blockM + wm + mt * 16 + g;
                int row1 = row0 + 8;
                if (row0 < NN) {
                    s0 += fmaxf(acc[mt][nt][0] + b0, 0.f);
                    s1 += fmaxf(acc[mt][nt][1] + b1, 0.f);
                }
                if (row1 < NN) {
                    s0 += fmaxf(acc[mt][nt][2] + b0, 0.f);
                    s1 += fmaxf(acc[mt][nt][3] + b1, 0.f);
                }
            }
            // reduce across g (lanes differing in bits 2..4)
#pragma unroll
            for (int o = 4; o < 32; o <<= 1) {
                s0 += __shfl_xor_sync(0xffffffffu, s0, o);
                s1 += __shfl_xor_sync(0xffffffffu, s1, o);
            }
            if (g == 0) {
                atomicAdd(&cs[col], s0);
                atomicAdd(&cs[col + 1], s1);
            }
        }
        __syncthreads();
        if (tid < 128) atomicAdd(&g_gsum[tid], cs[tid]);
    }
}

// ---------------- head: mu = g@W_mu + b_mu, lv = g@W_lv + b_lv --------------
__global__ void head_kernel(const float* __restrict__ Wmu, const float* __restrict__ bmu,
                            const float* __restrict__ Wlv, const float* __restrict__ blv,
                            float* __restrict__ out, int out_size) {
    int j = threadIdx.x;
    if (j >= 128 || j >= out_size) return;
    const float* W  = (j < 64) ? Wmu : Wlv;
    const float* bb = (j < 64) ? bmu : blv;
    int col = j & 63;
    const float invN = 1.0f / (float)NN;
    float s = 0.f;
#pragma unroll
    for (int f = 0; f < HID; f++)
        s += (g_gsum[f] * invN) * W[f * LAT + col];
    out[j] = s + bb[col];
}

// ---------------- launch -----------------------------------------------------
extern "C" void kernel_launch(void* const* d_in, const int* in_sizes, int n_in,
                              void* d_out, int out_size) {
    const float* x   = (const float*)d_in[0];
    const int*   ei  = (const int*)  d_in[1];
    const float* pe  = (const float*)d_in[2];
    const float* ew  = (const float*)d_in[3];
    const float* W1  = (const float*)d_in[4];
    const float* b1  = (const float*)d_in[5];
    const float* W2  = (const float*)d_in[6];
    const float* b2  = (const float*)d_in[7];
    const float* Wmu = (const float*)d_in[8];
    const float* bmu = (const float*)d_in[9];
    const float* Wlv = (const float*)d_in[10];
    const float* blv = (const float*)d_in[11];
    float* out = (float*)d_out;

    zero_kernel<<<(NN + 255) / 256, 256>>>();
    deg_cnt_kernel<<<(EE + 255) / 256, 256>>>(ei, ew);
    dinv_kernel<<<(NN + 255) / 256, 256>>>();
    scan1_kernel<<<SCAN_BLKS, 1024>>>(NN);
    scan2_kernel<<<1, 128>>>(SCAN_BLKS);
    scan3_kernel<<<SCAN_BLKS, 1024>>>(NN);
    cursor_init_kernel<<<(NN + 255) / 256, 256>>>();
    scatter_kernel<<<(EE + 255) / 256, 256>>>(ei, ew);
    build_h0_kernel<<<(NN * FIN + 255) / 256, 256>>>(x, pe);
    packW_kernel<<<((S1 / 2) * 128 + 255) / 256, 256>>>(W1, S1 / 2, 0);
    packW_kernel<<<((S2 / 2) * 128 + 255) / 256, 256>>>(W2, S2 / 2, 1);

    const int GEMM_BLOCKS = (NN + 127) / 128;
    const int SPMM_BLOCKS = (NN + 7) / 8;

    // ---- ChebConv 1 (F=144 -> 18 uint4 lanes, stride 576) ----
    spmm8h_kernel<<<SPMM_BLOCKS, 144>>>(0, S1, 18, 0,       FIN,     0,   0);
    spmm8h_kernel<<<SPMM_BLOCKS, 144>>>(0, S1, 18, FIN,     2 * FIN, 0,   1);
    spmm8h_kernel<<<SPMM_BLOCKS, 144>>>(0, S1, 18, 2 * FIN, 3 * FIN, FIN, 1);
    mma_gemm_kernel<0, S1, 18><<<GEMM_BLOCKS, 256>>>(b1);

    // ---- ChebConv 2 (F=128 -> 16 uint4 lanes, stride 512) ----
    spmm8h_kernel<<<SPMM_BLOCKS, 128>>>(1, S2, 16, 0,       HID,     0,   0);
    spmm8h_kernel<<<SPMM_BLOCKS, 128>>>(1, S2, 16, HID,     2 * HID, 0,   1);
    spmm8h_kernel<<<SPMM_BLOCKS, 128>>>(1, S2, 16, 2 * HID, 3 * HID, HID, 1);
    mma_gemm_kernel<1, S2, 16><<<GEMM_BLOCKS, 256>>>(b2);

    head_kernel<<<1, 128>>>(Wmu, bmu, Wlv, blv, out, out_size);
}

// round 6
// speedup vs baseline: 4.9589x; 1.1084x over previous
#include <cuda_runtime.h>
#include <cuda_fp16.h>
#include <cstdint>

#define NN  100000
#define EE  1600000
#define IND 128
#define PED 16
#define FIN 144
#define HID 128
#define LAT 64
#define S1  576   // 4*FIN
#define S2  512   // 4*HID
#define SCAN_BLKS ((NN + 1023) / 1024)

// ---------------- scratch (static device globals; no runtime allocation) ----
__device__ __half  g_T1[(size_t)NN * S1];   // [T0|T1|T2|T3] width FIN, fp16
__device__ __half  g_T2[(size_t)NN * S2];   // [T0|T1|T2|T3] width HID, fp16
__device__ __half2 g_W1p[(S1 / 2) * 128];   // W packed: [k2][n] = (W[2k2][n], W[2k2+1][n])
__device__ __half2 g_W2p[(S2 / 2) * 128];
__device__ float g_deg[NN];
__device__ float g_dinv[NN];
__device__ int   g_cnt[NN];
__device__ int   g_inc[NN];
__device__ int   g_rowptr[NN + 1];
__device__ int   g_cursor[NN];
__device__ int   g_bsum[128];
__device__ int   g_bexc[128];
__device__ int   g_csrc[EE];
__device__ float g_cw[EE];
__device__ float g_gsum[HID];

// ---------------- helpers ----------------------------------------------------
__device__ __forceinline__ void mma_f16(float* d, const uint32_t* a, const uint32_t* b) {
    asm volatile(
        "mma.sync.aligned.m16n8k16.row.col.f32.f16.f16.f32 "
        "{%0,%1,%2,%3}, {%4,%5,%6,%7}, {%8,%9}, {%0,%1,%2,%3};"
        : "+f"(d[0]), "+f"(d[1]), "+f"(d[2]), "+f"(d[3])
        : "r"(a[0]), "r"(a[1]), "r"(a[2]), "r"(a[3]), "r"(b[0]), "r"(b[1]));
}
__device__ __forceinline__ void cpa16(uint32_t dst, const void* src, uint32_t bytes) {
    asm volatile("cp.async.cg.shared.global [%0], [%1], 16, %2;"
                 :: "r"(dst), "l"(src), "r"(bytes));
}
#define CPA_COMMIT() asm volatile("cp.async.commit_group;" ::: "memory")
#define CPA_WAIT1()  asm volatile("cp.async.wait_group 1;" ::: "memory")

// ---------------- preprocessing kernels -------------------------------------
__global__ void zero_kernel() {
    int i = blockIdx.x * blockDim.x + threadIdx.x;
    if (i < NN) { g_deg[i] = 0.f; g_cnt[i] = 0; }
    if (i < HID) g_gsum[i] = 0.f;
}

__global__ void deg_cnt_kernel(const int* __restrict__ ei, const float* __restrict__ ew) {
    int e = blockIdx.x * blockDim.x + threadIdx.x;
    if (e >= EE) return;
    int s = ei[e], d = ei[EE + e];
    float w = ew[e];
    if (s == d) w = 0.f;                 // ChebConv removes self loops
    atomicAdd(&g_deg[s], w);
    atomicAdd(&g_cnt[d], 1);
}

// scan over cnt + dinv computation fused
__global__ void scan1_kernel(int n) {
    __shared__ int sh[1024];
    int tid = threadIdx.x;
    int i = blockIdx.x * 1024 + tid;
    if (i < n) {
        float dg = g_deg[i];
        g_dinv[i] = (dg > 0.f) ? rsqrtf(dg) : 0.f;
    }
    int v = (i < n) ? g_cnt[i] : 0;
    sh[tid] = v;
    __syncthreads();
    for (int off = 1; off < 1024; off <<= 1) {
        int t = (tid >= off) ? sh[tid - off] : 0;
        __syncthreads();
        sh[tid] += t;
        __syncthreads();
    }
    if (i < n) g_inc[i] = sh[tid];
    if (tid == 1023) g_bsum[blockIdx.x] = sh[1023];
}

__global__ void scan2_kernel(int nb) {
    __shared__ int sh[128];
    int tid = threadIdx.x;
    int v = (tid < nb) ? g_bsum[tid] : 0;
    sh[tid] = v;
    __syncthreads();
    for (int off = 1; off < 128; off <<= 1) {
        int t = (tid >= off) ? sh[tid - off] : 0;
        __syncthreads();
        sh[tid] += t;
        __syncthreads();
    }
    if (tid < nb) g_bexc[tid] = sh[tid] - v;   // exclusive block offsets
}

// rowptr + cursor init fused
__global__ void scan3_kernel(int n) {
    int i = blockIdx.x * 1024 + threadIdx.x;
    if (i < n) {
        int rp = g_inc[i] + g_bexc[blockIdx.x];
        g_rowptr[i + 1] = rp;
        if (i + 1 < n) g_cursor[i + 1] = rp;
    }
    if (i == 0) { g_rowptr[0] = 0; g_cursor[0] = 0; }
}

__global__ void scatter_kernel(const int* __restrict__ ei, const float* __restrict__ ew) {
    int e = blockIdx.x * blockDim.x + threadIdx.x;
    if (e >= EE) return;
    int s = ei[e], d = ei[EE + e];
    float w = ew[e];
    if (s == d) w = 0.f;
    float wh = -g_dinv[s] * w * g_dinv[d];   // L_hat = -D^-1/2 A D^-1/2
    int pos = atomicAdd(&g_cursor[d], 1);
    g_csrc[pos] = s;
    g_cw[pos]   = wh;
}

// h0 build: 8 features per thread, vectorized
__global__ void build_h0_kernel(const float* __restrict__ x, const float* __restrict__ pe) {
    int idx = blockIdx.x * blockDim.x + threadIdx.x;
    if (idx >= NN * 18) return;
    int i = idx / 18, l = idx - i * 18;
    float4 a, b;
    if (l < 16) {
        const float4* px = reinterpret_cast<const float4*>(x + (size_t)i * IND + l * 8);
        a = px[0]; b = px[1];
    } else {
        const float4* pp = reinterpret_cast<const float4*>(pe + (size_t)i * PED + (l - 16) * 8);
        a = pp[0]; b = pp[1];
    }
    uint4 o;
    __half2* ho = reinterpret_cast<__half2*>(&o);
    ho[0] = __floats2half2_rn(a.x, a.y);
    ho[1] = __floats2half2_rn(a.z, a.w);
    ho[2] = __floats2half2_rn(b.x, b.y);
    ho[3] = __floats2half2_rn(b.z, b.w);
    *reinterpret_cast<uint4*>(g_T1 + (size_t)i * S1 + l * 8) = o;
}

__global__ void packW_kernel(const float* __restrict__ W, int K2, int which) {
    int idx = blockIdx.x * blockDim.x + threadIdx.x;
    if (idx >= K2 * 128) return;
    int k2 = idx >> 7, n = idx & 127;
    __half2 h = __floats2half2_rn(W[(size_t)(2 * k2) * 128 + n],
                                  W[(size_t)(2 * k2 + 1) * 128 + n]);
    (which ? g_W2p : g_W1p)[idx] = h;
}

// ---------------- SpMM (half, uint4 = 8 feats/lane, unroll 4) ---------------
__global__ void spmm8h_kernel(int whichBuf, int S, int LANES,
                              int inOff, int outOff, int prevOff, int recur) {
    __half* T = whichBuf ? g_T2 : g_T1;
    int tid = threadIdx.x;
    int r  = tid / LANES;
    int f8 = tid - r * LANES;
    int i = blockIdx.x * 8 + r;
    if (i >= NN) return;
    int beg = g_rowptr[i], end = g_rowptr[i + 1];
    const __half* Tin = T + inOff + f8 * 8;
    float acc[8];
#pragma unroll
    for (int q = 0; q < 8; q++) acc[q] = 0.f;
    int e = beg;
    for (; e + 4 <= end; e += 4) {
        int s0 = __ldg(&g_csrc[e]),     s1 = __ldg(&g_csrc[e + 1]);
        int s2 = __ldg(&g_csrc[e + 2]), s3 = __ldg(&g_csrc[e + 3]);
        float w0 = __ldg(&g_cw[e]),     w1 = __ldg(&g_cw[e + 1]);
        float w2 = __ldg(&g_cw[e + 2]), w3 = __ldg(&g_cw[e + 3]);
        uint4 v0 = __ldg(reinterpret_cast<const uint4*>(Tin + (size_t)s0 * S));
        uint4 v1 = __ldg(reinterpret_cast<const uint4*>(Tin + (size_t)s1 * S));
        uint4 v2 = __ldg(reinterpret_cast<const uint4*>(Tin + (size_t)s2 * S));
        uint4 v3 = __ldg(reinterpret_cast<const uint4*>(Tin + (size_t)s3 * S));
        const __half2* h0 = reinterpret_cast<const __half2*>(&v0);
        const __half2* h1 = reinterpret_cast<const __half2*>(&v1);
        const __half2* h2 = reinterpret_cast<const __half2*>(&v2);
        const __half2* h3 = reinterpret_cast<const __half2*>(&v3);
#pragma unroll
        for (int q = 0; q < 4; q++) {
            float2 a = __half22float2(h0[q]);
            float2 b = __half22float2(h1[q]);
            float2 c = __half22float2(h2[q]);
            float2 d = __half22float2(h3[q]);
            acc[2 * q]     += (w0 * a.x + w1 * b.x) + (w2 * c.x + w3 * d.x);
            acc[2 * q + 1] += (w0 * a.y + w1 * b.y) + (w2 * c.y + w3 * d.y);
        }
    }
    for (; e < end; ++e) {
        int s0 = __ldg(&g_csrc[e]);
        float w0 = __ldg(&g_cw[e]);
        uint4 v0 = __ldg(reinterpret_cast<const uint4*>(Tin + (size_t)s0 * S));
        const __half2* h0 = reinterpret_cast<const __half2*>(&v0);
#pragma unroll
        for (int q = 0; q < 4; q++) {
            float2 a = __half22float2(h0[q]);
            acc[2 * q]     += w0 * a.x;
            acc[2 * q + 1] += w0 * a.y;
        }
    }
    if (recur) {
        uint4 pv = *reinterpret_cast<const uint4*>(T + (size_t)i * S + prevOff + f8 * 8);
        const __half2* hp = reinterpret_cast<const __half2*>(&pv);
#pragma unroll
        for (int q = 0; q < 4; q++) {
            float2 p = __half22float2(hp[q]);
            acc[2 * q]     = 2.f * acc[2 * q]     - p.x;
            acc[2 * q + 1] = 2.f * acc[2 * q + 1] - p.y;
        }
    }
    uint4 o;
    __half2* ho = reinterpret_cast<__half2*>(&o);
#pragma unroll
    for (int q = 0; q < 4; q++)
        ho[q] = __floats2half2_rn(acc[2 * q], acc[2 * q + 1]);
    *reinterpret_cast<uint4*>(T + (size_t)i * S + outOff + f8 * 8) = o;
}

// ---------------- fp16 mma.sync GEMM, cp.async double-buffered ---------------
// MODE 0: A = g_T1 [NN, K=576] half; write half to g_T2 slice0 (stride S2)
// MODE 1: A = g_T2 [NN, K=512] half; column-sum into g_gsum (no store of C)
template <int MODE, int K, int NKT>
__global__ void __launch_bounds__(256)
mma_gemm_kernel(const float* __restrict__ bias) {
    const __half*  A  = (MODE == 0) ? g_T1 : g_T2;
    const __half2* Wp = (MODE == 0) ? g_W1p : g_W2p;
    __shared__ alignas(16) __half  As[2][128 * 40];   // [row][k], stride 40 halves
    __shared__ alignas(16) __half2 Bs[2][16 * 136];   // [k2][n],  stride 136 half2
    __shared__ float cs[128];

    int tid = threadIdx.x;
    int lane = tid & 31, wid = tid >> 5;
    int wm = (wid & 1) * 64;        // warp M offset
    int wn = (wid >> 1) * 32;       // warp N offset
    int blockM = blockIdx.x * 128;
    int g = lane >> 2, c = lane & 3;

    // per-thread load coordinates
    int aRow = tid >> 2, aQ = tid & 3;               // A: rows [aRow, aRow+64]
    int bK2 = tid >> 5, bN4 = tid & 31;              // B: k2 [bK2, bK2+8]
    int gr0 = blockM + aRow, gr1 = gr0 + 64;
    uint32_t szA0 = (gr0 < NN) ? 16u : 0u;
    uint32_t szA1 = (gr1 < NN) ? 16u : 0u;
    uint32_t dA0[2], dA1[2], dB0[2], dB1[2];
#pragma unroll
    for (int s = 0; s < 2; s++) {
        dA0[s] = (uint32_t)__cvta_generic_to_shared(&As[s][aRow * 40 + aQ * 8]);
        dA1[s] = (uint32_t)__cvta_generic_to_shared(&As[s][(aRow + 64) * 40 + aQ * 8]);
        dB0[s] = (uint32_t)__cvta_generic_to_shared(&Bs[s][bK2 * 136 + bN4 * 4]);
        dB1[s] = (uint32_t)__cvta_generic_to_shared(&Bs[s][(bK2 + 8) * 136 + bN4 * 4]);
    }

    float acc[4][4][4];
#pragma unroll
    for (int mt = 0; mt < 4; mt++)
#pragma unroll
        for (int nt = 0; nt < 4; nt++)
#pragma unroll
            for (int q = 0; q < 4; q++) acc[mt][nt][q] = 0.f;

    if (MODE == 1 && tid < 128) cs[tid] = 0.f;

    // prologue: stage 0
    {
        int kc = 0, kc2 = 0;
        cpa16(dA0[0], &A[(size_t)gr0 * K + kc + aQ * 8], szA0);
        cpa16(dA1[0], &A[(size_t)gr1 * K + kc + aQ * 8], szA1);
        cpa16(dB0[0], &Wp[(size_t)(kc2 + bK2) * 128 + bN4 * 4], 16u);
        cpa16(dB1[0], &Wp[(size_t)(kc2 + bK2 + 8) * 128 + bN4 * 4], 16u);
    }
    CPA_COMMIT();

    for (int kt = 0; kt < NKT; kt++) {
        if (kt + 1 < NKT) {
            int kc = (kt + 1) * 32, kc2 = (kt + 1) * 16;
            int buf = (kt + 1) & 1;
            cpa16(dA0[buf], &A[(size_t)gr0 * K + kc + aQ * 8], szA0);
            cpa16(dA1[buf], &A[(size_t)gr1 * K + kc + aQ * 8], szA1);
            cpa16(dB0[buf], &Wp[(size_t)(kc2 + bK2) * 128 + bN4 * 4], 16u);
            cpa16(dB1[buf], &Wp[(size_t)(kc2 + bK2 + 8) * 128 + bN4 * 4], 16u);
        }
        CPA_COMMIT();
        CPA_WAIT1();
        __syncthreads();

        const uint32_t* As32 = reinterpret_cast<const uint32_t*>(As[kt & 1]);
        const uint32_t* Bs32 = reinterpret_cast<const uint32_t*>(Bs[kt & 1]);
#pragma unroll
        for (int ks = 0; ks < 2; ks++) {    // two k16 steps per 32-chunk
            int k2b = ks * 8;
            uint32_t a[4][4];
#pragma unroll
            for (int mt = 0; mt < 4; mt++) {
                int row = wm + mt * 16 + g;
                a[mt][0] = As32[row * 20 + k2b + c];
                a[mt][1] = As32[(row + 8) * 20 + k2b + c];
                a[mt][2] = As32[row * 20 + k2b + c + 4];
                a[mt][3] = As32[(row + 8) * 20 + k2b + c + 4];
            }
            uint32_t b[4][2];
#pragma unroll
            for (int nt = 0; nt < 4; nt++) {
                int col = wn + nt * 8 + g;
                b[nt][0] = Bs32[(k2b + c) * 136 + col];
                b[nt][1] = Bs32[(k2b + c + 4) * 136 + col];
            }
#pragma unroll
            for (int mt = 0; mt < 4; mt++)
#pragma unroll
                for (int nt = 0; nt < 4; nt++)
                    mma_f16(acc[mt][nt], a[mt], b[nt]);
        }
        __syncthreads();
    }

    // ---- epilogue ----
    if (MODE == 0) {
#pragma unroll
        for (int mt = 0; mt < 4; mt++) {
#pragma unroll
            for (int nt = 0; nt < 4; nt++) {
                int col = wn + nt * 8 + 2 * c;
                float b0 = bias[col], b1 = bias[col + 1];
                int row0 = blockM + wm + mt * 16 + g;
                int row1 = row0 + 8;
                if (row0 < NN) {
                    __half2 o = __floats2half2_rn(fmaxf(acc[mt][nt][0] + b0, 0.f),
                                                  fmaxf(acc[mt][nt][1] + b1, 0.f));
                    *reinterpret_cast<__half2*>(&g_T2[(size_t)row0 * S2 + col]) = o;
                }
                if (row1 < NN) {
                    __half2 o = __floats2half2_rn(fmaxf(acc[mt][nt][2] + b0, 0.f),
                                                  fmaxf(acc[mt][nt][3] + b1, 0.f));
                    *reinterpret_cast<__half2*>(&g_T2[(size_t)row1 * S2 + col]) = o;
                }
            }
        }
    } else {
#pragma unroll
        for (int nt = 0; nt < 4; nt++) {
            int col = wn + nt * 8 + 2 * c;
            float b0 = bias[col], b1 = bias[col + 1];
            float s0 = 0.f, s1 = 0.f;
#pragma unroll
            for (int mt = 0; mt < 4; mt++) {
                int row0 = blockM + wm + mt * 16 + g;
                int row1 = row0 + 8;
                if (row0 < NN) {
                    s0 += fmaxf(acc[mt][nt][0] + b0, 0.f);
                    s1 += fmaxf(acc[mt][nt][1] + b1, 0.f);
                }
                if (row1 < NN) {
                    s0 += fmaxf(acc[mt][nt][2] + b0, 0.f);
                    s1 += fmaxf(acc[mt][nt][3] + b1, 0.f);
                }
            }
#pragma unroll
            for (int o = 4; o < 32; o <<= 1) {
                s0 += __shfl_xor_sync(0xffffffffu, s0, o);
                s1 += __shfl_xor_sync(0xffffffffu, s1, o);
            }
            if (g == 0) {
                atomicAdd(&cs[col], s0);
                atomicAdd(&cs[col + 1], s1);
            }
        }
        __syncthreads();
        if (tid < 128) atomicAdd(&g_gsum[tid], cs[tid]);
    }
}

// ---------------- head: mu = g@W_mu + b_mu, lv = g@W_lv + b_lv --------------
__global__ void head_kernel(const float* __restrict__ Wmu, const float* __restrict__ bmu,
                            const float* __restrict__ Wlv, const float* __restrict__ blv,
                            float* __restrict__ out, int out_size) {
    int j = threadIdx.x;
    if (j >= 128 || j >= out_size) return;
    const float* W  = (j < 64) ? Wmu : Wlv;
    const float* bb = (j < 64) ? bmu : blv;
    int col = j & 63;
    const float invN = 1.0f / (float)NN;
    float s = 0.f;
#pragma unroll
    for (int f = 0; f < HID; f++)
        s += (g_gsum[f] * invN) * W[f * LAT + col];
    out[j] = s + bb[col];
}

// ---------------- launch -----------------------------------------------------
extern "C" void kernel_launch(void* const* d_in, const int* in_sizes, int n_in,
                              void* d_out, int out_size) {
    const float* x   = (const float*)d_in[0];
    const int*   ei  = (const int*)  d_in[1];
    const float* pe  = (const float*)d_in[2];
    const float* ew  = (const float*)d_in[3];
    const float* W1  = (const float*)d_in[4];
    const float* b1  = (const float*)d_in[5];
    const float* W2  = (const float*)d_in[6];
    const float* b2  = (const float*)d_in[7];
    const float* Wmu = (const float*)d_in[8];
    const float* bmu = (const float*)d_in[9];
    const float* Wlv = (const float*)d_in[10];
    const float* blv = (const float*)d_in[11];
    float* out = (float*)d_out;

    zero_kernel<<<(NN + 255) / 256, 256>>>();
    deg_cnt_kernel<<<(EE + 255) / 256, 256>>>(ei, ew);
    scan1_kernel<<<SCAN_BLKS, 1024>>>(NN);
    scan2_kernel<<<1, 128>>>(SCAN_BLKS);
    scan3_kernel<<<SCAN_BLKS, 1024>>>(NN);
    scatter_kernel<<<(EE + 255) / 256, 256>>>(ei, ew);
    build_h0_kernel<<<(NN * 18 + 255) / 256, 256>>>(x, pe);
    packW_kernel<<<((S1 / 2) * 128 + 255) / 256, 256>>>(W1, S1 / 2, 0);
    packW_kernel<<<((S2 / 2) * 128 + 255) / 256, 256>>>(W2, S2 / 2, 1);

    const int GEMM_BLOCKS = (NN + 127) / 128;
    const int SPMM_BLOCKS = (NN + 7) / 8;

    // ---- ChebConv 1 (F=144 -> 18 uint4 lanes, stride 576) ----
    spmm8h_kernel<<<SPMM_BLOCKS, 144>>>(0, S1, 18, 0,       FIN,     0,   0);
    spmm8h_kernel<<<SPMM_BLOCKS, 144>>>(0, S1, 18, FIN,     2 * FIN, 0,   1);
    spmm8h_kernel<<<SPMM_BLOCKS, 144>>>(0, S1, 18, 2 * FIN, 3 * FIN, FIN, 1);
    mma_gemm_kernel<0, S1, 18><<<GEMM_BLOCKS, 256>>>(b1);

    // ---- ChebConv 2 (F=128 -> 16 uint4 lanes, stride 512) ----
    spmm8h_kernel<<<SPMM_BLOCKS, 128>>>(1, S2, 16, 0,       HID,     0,   0);
    spmm8h_kernel<<<SPMM_BLOCKS, 128>>>(1, S2, 16, HID,     2 * HID, 0,   1);
    spmm8h_kernel<<<SPMM_BLOCKS, 128>>>(1, S2, 16, 2 * HID, 3 * HID, HID, 1);
    mma_gemm_kernel<1, S2, 16><<<GEMM_BLOCKS, 256>>>(b2);

    head_kernel<<<1, 128>>>(Wmu, bmu, Wlv, blv, out, out_size);
}